// round 4
// baseline (speedup 1.0000x reference)
#include <cuda_runtime.h>
#include <cuda_bf16.h>

// LightConv: out[b,t,h*S+s] = sum_k softmax_k(filters[b,t,h*K+k]) * x[b, t+k-PAD, h*S+s] + bias[h*S+s]
// B=8 T=1024 H=8 S=64 K=31 C=512

#define B_ 8
#define T_ 1024
#define H_ 8
#define S_ 64
#define K_ 31
#define C_ 512
#define HK_ (H_ * K_)      // 248
#define PAD_ 15            // K/2
#define TTILE 64           // t rows per CTA (small CTA -> fine-grained wave balance)
#define RT 8               // t outputs per thread
#define NTHREADS 128       // 8 t-groups x 16 float4 lanes
#define XROWS (TTILE + 2 * PAD_)   // 94
#define WSTRIDE 65         // f32 weights, k-major: ws[k*65 + row], conflict-free

// xs: 94*64*4 = 24064 B ; ws: 31*65*4 = 8060 B ; total 32124 B -> 6 CTAs/SM (192.7 KB)
#define SMEM_BYTES (XROWS * S_ * 4 + K_ * WSTRIDE * 4)

typedef unsigned long long u64;

__device__ __forceinline__ u64 pack2(float w) {
    u64 d;
    asm("mov.b64 %0, {%1, %1};" : "=l"(d) : "f"(w));
    return d;
}
__device__ __forceinline__ u64 pack2f(float a, float b) {
    u64 d;
    asm("mov.b64 %0, {%1, %2};" : "=l"(d) : "f"(a), "f"(b));
    return d;
}
__device__ __forceinline__ void fma2(u64& a, u64 x, u64 w) {
    asm("fma.rn.f32x2 %0, %1, %2, %3;" : "=l"(a) : "l"(x), "l"(w), "l"(a));
}
__device__ __forceinline__ float2 unpack2(u64 v) {
    float2 f;
    asm("mov.b64 {%0, %1}, %2;" : "=f"(f.x), "=f"(f.y) : "l"(v));
    return f;
}

__global__ __launch_bounds__(NTHREADS, 6) void lightconv_kernel(
    const float* __restrict__ x,
    const float* __restrict__ filters,
    const float* __restrict__ bias,
    float* __restrict__ out)
{
    extern __shared__ float smem[];
    float* xs = smem;                    // [XROWS][64]
    float* ws = smem + XROWS * S_;       // k-major f32: [K][WSTRIDE]

    const int t0   = blockIdx.x * TTILE;
    const int h    = blockIdx.y;
    const int b    = blockIdx.z;
    const int tid  = threadIdx.x;
    const int lane = tid & 31;
    const int warp = tid >> 5;

    // ---- load x tile (coalesced), zero-fill halo outside [0, T) ----
    const float* xbase = x + (size_t)b * T_ * C_ + h * S_;
    #pragma unroll 4
    for (int idx = tid; idx < XROWS * S_; idx += NTHREADS) {
        int row = idx >> 6;
        int col = idx & 63;
        int t   = t0 + row - PAD_;
        float v = 0.0f;
        if (t >= 0 && t < T_) v = xbase[(size_t)t * C_ + col];
        xs[idx] = v;
    }

    // ---- softmax over K=31 taps: warp per t-row, lane = k; 2 rows/iter for ILP ----
    const float* fbase = filters + (size_t)b * T_ * HK_ + h * K_;
    for (int row = warp; row < TTILE; row += 8) {
        int rowB = row + 4;
        float fA = -1e30f, fB = -1e30f;
        if (lane < K_) {
            fA = fbase[(size_t)(t0 + row)  * HK_ + lane];
            fB = fbase[(size_t)(t0 + rowB) * HK_ + lane];
        }
        float mA = fA, mB = fB;
        #pragma unroll
        for (int o = 16; o > 0; o >>= 1) {
            mA = fmaxf(mA, __shfl_xor_sync(0xffffffffu, mA, o));
            mB = fmaxf(mB, __shfl_xor_sync(0xffffffffu, mB, o));
        }
        float eA = (lane < K_) ? __expf(fA - mA) : 0.0f;
        float eB = (lane < K_) ? __expf(fB - mB) : 0.0f;
        float sA = eA, sB = eB;
        #pragma unroll
        for (int o = 16; o > 0; o >>= 1) {
            sA += __shfl_xor_sync(0xffffffffu, sA, o);
            sB += __shfl_xor_sync(0xffffffffu, sB, o);
        }
        if (lane < K_) {
            ws[lane * WSTRIDE + row]  = eA * (1.0f / sA);   // bank = (lane+row)%32 -> conflict-free
            ws[lane * WSTRIDE + rowB] = eB * (1.0f / sB);
        }
        row += 8;  // handled rowB already? no — rowB = row+4; loop step handles next 8
        row -= 8;  // (keep loop increment semantics; step is 8, pairs (row,row+4))
    }
    __syncthreads();

    // ---- main product ----
    // thread = (s4: 4 channels as 2x f32x2) x (tg: RT t outputs)
    const int s4 = tid & 15;
    const int tg = tid >> 4;       // 0..7
    const int tl = tg * RT;

    const ulonglong2* xs2 = reinterpret_cast<const ulonglong2*>(xs) + s4;
    const float* wcol = ws + tl;   // w[t=tl+r][k=j-r] at wcol[(j-r)*WSTRIDE + r]

    // init accumulators with bias (saves the epilogue FADDs)
    float4 bv = reinterpret_cast<const float4*>(bias + h * S_)[s4];
    u64 acc[RT][2];
    #pragma unroll
    for (int r = 0; r < RT; ++r) {
        acc[r][0] = pack2f(bv.x, bv.y);
        acc[r][1] = pack2f(bv.z, bv.w);
    }

    // Region 1: j = 0 .. RT-2 (triangular, compile-time guards)
    #pragma unroll
    for (int j = 0; j < RT - 1; ++j) {
        ulonglong2 xv = xs2[(tl + j) * (S_ / 4)];
        #pragma unroll
        for (int r = 0; r < RT; ++r) {
            if (r <= j) {
                u64 w2 = pack2(wcol[(j - r) * WSTRIDE + r]);
                fma2(acc[r][0], xv.x, w2);
                fma2(acc[r][1], xv.y, w2);
            }
        }
    }

    // Region 2: j = RT-1 .. K-1 (steady state: no predicates)
    #pragma unroll 4
    for (int j = RT - 1; j < K_; ++j) {
        ulonglong2 xv = xs2[(tl + j) * (S_ / 4)];
        #pragma unroll
        for (int r = 0; r < RT; ++r) {
            u64 w2 = pack2(wcol[(j - r) * WSTRIDE + r]);
            fma2(acc[r][0], xv.x, w2);
            fma2(acc[r][1], xv.y, w2);
        }
    }

    // Region 3: j = K .. K+RT-2 (triangular, compile-time guards)
    #pragma unroll
    for (int j = K_; j < K_ + RT - 1; ++j) {
        ulonglong2 xv = xs2[(tl + j) * (S_ / 4)];
        #pragma unroll
        for (int r = 0; r < RT; ++r) {
            if (j - r < K_) {
                u64 w2 = pack2(wcol[(j - r) * WSTRIDE + r]);
                fma2(acc[r][0], xv.x, w2);
                fma2(acc[r][1], xv.y, w2);
            }
        }
    }

    // ---- epilogue: vectorized store (bias already folded in) ----
    float4* outbase = reinterpret_cast<float4*>(
        out + ((size_t)b * T_ + t0 + tl) * C_ + h * S_) + s4;
    #pragma unroll
    for (int r = 0; r < RT; ++r) {
        float2 lo = unpack2(acc[r][0]);
        float2 hi = unpack2(acc[r][1]);
        float4 o;
        o.x = lo.x;
        o.y = lo.y;
        o.z = hi.x;
        o.w = hi.y;
        outbase[(size_t)r * (C_ / 4)] = o;
    }
}

extern "C" void kernel_launch(void* const* d_in, const int* in_sizes, int n_in,
                              void* d_out, int out_size)
{
    const float* x       = (const float*)d_in[0];
    const float* filters = (const float*)d_in[1];
    const float* bias    = (const float*)d_in[2];
    float* out           = (float*)d_out;

    cudaFuncSetAttribute(lightconv_kernel,
                         cudaFuncAttributeMaxDynamicSharedMemorySize, SMEM_BYTES);

    dim3 grid(T_ / TTILE, H_, B_);   // (16, 8, 8) = 1024 CTAs -> ~6.9 per SM, tail ~1%
    lightconv_kernel<<<grid, NTHREADS, SMEM_BYTES>>>(x, filters, bias, out);
}

// round 5
// speedup vs baseline: 1.4006x; 1.4006x over previous
#include <cuda_runtime.h>
#include <cuda_bf16.h>

// LightConv: out[b,t,h*S+s] = sum_k softmax_k(filters[b,t,h*K+k]) * x[b, t+k-PAD, h*S+s] + bias[h*S+s]
// B=8 T=1024 H=8 S=64 K=31 C=512

#define B_ 8
#define T_ 1024
#define H_ 8
#define S_ 64
#define K_ 31
#define C_ 512
#define HK_ (H_ * K_)      // 248
#define PAD_ 15            // K/2
#define TTILE 128          // t rows per CTA
#define RT 8               // t outputs per thread
#define NTHREADS 256       // 16 t-groups x 16 float4 lanes
#define XROWS (TTILE + 2 * PAD_)   // 158
#define WSTRIDE 129        // f32 weights, k-major: ws[k*129 + row], conflict-free

// xs: 158*64*4 = 40448 B ; ws: 31*129*4 = 15996 B ; total 56444 B -> 3 CTAs/SM
#define SMEM_BYTES (XROWS * S_ * 4 + K_ * WSTRIDE * 4)

typedef unsigned long long u64;

__device__ __forceinline__ u64 pack2(float w) {
    u64 d;
    asm("mov.b64 %0, {%1, %1};" : "=l"(d) : "f"(w));
    return d;
}
__device__ __forceinline__ u64 pack2f(float a, float b) {
    u64 d;
    asm("mov.b64 %0, {%1, %2};" : "=l"(d) : "f"(a), "f"(b));
    return d;
}
__device__ __forceinline__ void fma2(u64& a, u64 x, u64 w) {
    asm("fma.rn.f32x2 %0, %1, %2, %3;" : "=l"(a) : "l"(x), "l"(w), "l"(a));
}
__device__ __forceinline__ float2 unpack2(u64 v) {
    float2 f;
    asm("mov.b64 {%0, %1}, %2;" : "=f"(f.x), "=f"(f.y) : "l"(v));
    return f;
}

__global__ __launch_bounds__(NTHREADS, 3) void lightconv_kernel(
    const float* __restrict__ x,
    const float* __restrict__ filters,
    const float* __restrict__ bias,
    float* __restrict__ out)
{
    extern __shared__ float smem[];
    float* xs = smem;                    // [XROWS][64]
    float* ws = smem + XROWS * S_;       // k-major f32: [K][WSTRIDE]

    const int t0   = blockIdx.x * TTILE;
    const int h    = blockIdx.y;
    const int b    = blockIdx.z;
    const int tid  = threadIdx.x;
    const int lane = tid & 31;
    const int warp = tid >> 5;

    // ---- load x tile with float4 (10 LDG.128 / thread), zero-fill halo ----
    // XROWS*16 = 2528 float4 slots, 256 threads -> 9.875 iters
    const float4* xbase4 = reinterpret_cast<const float4*>(x + (size_t)b * T_ * C_ + h * S_);
    float4* xs4w = reinterpret_cast<float4*>(xs);
    #pragma unroll 5
    for (int idx = tid; idx < XROWS * 16; idx += NTHREADS) {
        int row  = idx >> 4;         // /16
        int col4 = idx & 15;
        int t    = t0 + row - PAD_;
        float4 v = make_float4(0.f, 0.f, 0.f, 0.f);
        if (t >= 0 && t < T_) v = xbase4[(size_t)t * (C_ / 4) + col4];
        xs4w[idx] = v;
    }

    // ---- softmax over K=31 taps: warp per t-row, lane = k; 2 rows/iter for ILP ----
    const float* fbase = filters + (size_t)b * T_ * HK_ + h * K_;
    for (int row = warp; row < TTILE; row += 16) {
        int rowB = row + 8;
        float fA = -1e30f, fB = -1e30f;
        if (lane < K_) {
            fA = fbase[(size_t)(t0 + row)  * HK_ + lane];
            fB = fbase[(size_t)(t0 + rowB) * HK_ + lane];
        }
        float mA = fA, mB = fB;
        #pragma unroll
        for (int o = 16; o > 0; o >>= 1) {
            mA = fmaxf(mA, __shfl_xor_sync(0xffffffffu, mA, o));
            mB = fmaxf(mB, __shfl_xor_sync(0xffffffffu, mB, o));
        }
        float eA = (lane < K_) ? __expf(fA - mA) : 0.0f;
        float eB = (lane < K_) ? __expf(fB - mB) : 0.0f;
        float sA = eA, sB = eB;
        #pragma unroll
        for (int o = 16; o > 0; o >>= 1) {
            sA += __shfl_xor_sync(0xffffffffu, sA, o);
            sB += __shfl_xor_sync(0xffffffffu, sB, o);
        }
        if (lane < K_) {
            ws[lane * WSTRIDE + row]  = eA * (1.0f / sA);   // bank=(lane+row)%32 conflict-free
            ws[lane * WSTRIDE + rowB] = eB * (1.0f / sB);
        }
    }
    __syncthreads();

    // ---- main product ----
    // thread = (s4: 4 channels as 2x f32x2) x (tg: RT t outputs)
    const int s4 = tid & 15;
    const int tg = tid >> 4;
    const int tl = tg * RT;

    const ulonglong2* xs2 = reinterpret_cast<const ulonglong2*>(xs) + s4;
    const float* wcol = ws + tl;   // w[t=tl+r][k=j-r] at wcol[(j-r)*WSTRIDE + r]

    // init accumulators with bias (epilogue FADDs folded away)
    float4 bv = reinterpret_cast<const float4*>(bias + h * S_)[s4];
    u64 acc[RT][2];
    #pragma unroll
    for (int r = 0; r < RT; ++r) {
        acc[r][0] = pack2f(bv.x, bv.y);
        acc[r][1] = pack2f(bv.z, bv.w);
    }

    // Region 1: j = 0 .. RT-2 (triangular, compile-time guards)
    #pragma unroll
    for (int j = 0; j < RT - 1; ++j) {
        ulonglong2 xv = xs2[(tl + j) * (S_ / 4)];
        #pragma unroll
        for (int r = 0; r < RT; ++r) {
            if (r <= j) {
                u64 w2 = pack2(wcol[(j - r) * WSTRIDE + r]);
                fma2(acc[r][0], xv.x, w2);
                fma2(acc[r][1], xv.y, w2);
            }
        }
    }

    // Region 2: j = RT-1 .. K-1 (steady state: no predicates, fully unrolled
    // so ptxas can pipeline weight LDS across FMA groups with the 85-reg budget)
    #pragma unroll
    for (int j = RT - 1; j < K_; ++j) {
        ulonglong2 xv = xs2[(tl + j) * (S_ / 4)];
        #pragma unroll
        for (int r = 0; r < RT; ++r) {
            u64 w2 = pack2(wcol[(j - r) * WSTRIDE + r]);
            fma2(acc[r][0], xv.x, w2);
            fma2(acc[r][1], xv.y, w2);
        }
    }

    // Region 3: j = K .. K+RT-2 (triangular, compile-time guards)
    #pragma unroll
    for (int j = K_; j < K_ + RT - 1; ++j) {
        ulonglong2 xv = xs2[(tl + j) * (S_ / 4)];
        #pragma unroll
        for (int r = 0; r < RT; ++r) {
            if (j - r < K_) {
                u64 w2 = pack2(wcol[(j - r) * WSTRIDE + r]);
                fma2(acc[r][0], xv.x, w2);
                fma2(acc[r][1], xv.y, w2);
            }
        }
    }

    // ---- epilogue: vectorized store (bias already folded in) ----
    float4* outbase = reinterpret_cast<float4*>(
        out + ((size_t)b * T_ + t0 + tl) * C_ + h * S_) + s4;
    #pragma unroll
    for (int r = 0; r < RT; ++r) {
        float2 lo = unpack2(acc[r][0]);
        float2 hi = unpack2(acc[r][1]);
        float4 o;
        o.x = lo.x;
        o.y = lo.y;
        o.z = hi.x;
        o.w = hi.y;
        outbase[(size_t)r * (C_ / 4)] = o;
    }
}

extern "C" void kernel_launch(void* const* d_in, const int* in_sizes, int n_in,
                              void* d_out, int out_size)
{
    const float* x       = (const float*)d_in[0];
    const float* filters = (const float*)d_in[1];
    const float* bias    = (const float*)d_in[2];
    float* out           = (float*)d_out;

    cudaFuncSetAttribute(lightconv_kernel,
                         cudaFuncAttributeMaxDynamicSharedMemorySize, SMEM_BYTES);

    dim3 grid(T_ / TTILE, H_, B_);   // (8, 8, 8) = 512 CTAs, 3 CTAs/SM -> 1.15 waves
    lightconv_kernel<<<grid, NTHREADS, SMEM_BYTES>>>(x, filters, bias, out);
}

// round 6
// speedup vs baseline: 1.7039x; 1.2166x over previous
#include <cuda_runtime.h>
#include <cuda_bf16.h>

// LightConv: out[b,t,h*S+s] = sum_k softmax_k(filters[b,t,h*K+k]) * x[b, t+k-PAD, h*S+s] + bias[h*S+s]
// B=8 T=1024 H=8 S=64 K=31 C=512

#define B_ 8
#define T_ 1024
#define H_ 8
#define S_ 64
#define K_ 31
#define C_ 512
#define HK_ (H_ * K_)      // 248
#define PAD_ 15            // K/2
#define TTILE 128          // t rows per CTA
#define RT 8               // t outputs per thread
#define NTHREADS 256       // 16 t-groups x 16 float4 lanes
#define XROWS (TTILE + 2 * PAD_)   // 158
#define WSTRIDE 129        // f32 weights, k-major: ws[k*129 + row], conflict-free

// xs: 158*64*4 = 40448 B ; ws: 31*129*4 = 15996 B ; total 56444 B
// 4 CTAs/SM: smem 225,776 B (fits 228K carveout), regs 64*1024 = 65536 (exact fit)
#define SMEM_BYTES (XROWS * S_ * 4 + K_ * WSTRIDE * 4)

typedef unsigned long long u64;

__device__ __forceinline__ u64 pack2(float w) {
    u64 d;
    asm("mov.b64 %0, {%1, %1};" : "=l"(d) : "f"(w));
    return d;
}
__device__ __forceinline__ u64 pack2f(float a, float b) {
    u64 d;
    asm("mov.b64 %0, {%1, %2};" : "=l"(d) : "f"(a), "f"(b));
    return d;
}
__device__ __forceinline__ void fma2(u64& a, u64 x, u64 w) {
    asm("fma.rn.f32x2 %0, %1, %2, %3;" : "=l"(a) : "l"(x), "l"(w), "l"(a));
}
__device__ __forceinline__ float2 unpack2(u64 v) {
    float2 f;
    asm("mov.b64 {%0, %1}, %2;" : "=f"(f.x), "=f"(f.y) : "l"(v));
    return f;
}

__global__ __launch_bounds__(NTHREADS, 4) void lightconv_kernel(
    const float* __restrict__ x,
    const float* __restrict__ filters,
    const float* __restrict__ bias,
    float* __restrict__ out)
{
    extern __shared__ float smem[];
    float* xs = smem;                    // [XROWS][64]
    float* ws = smem + XROWS * S_;       // k-major f32: [K][WSTRIDE]

    const int t0   = blockIdx.x * TTILE;
    const int h    = blockIdx.y;
    const int b    = blockIdx.z;
    const int tid  = threadIdx.x;
    const int lane = tid & 31;
    const int warp = tid >> 5;

    // ---- load x tile with float4 (10 LDG.128 / thread), zero-fill halo ----
    const float4* xbase4 = reinterpret_cast<const float4*>(x + (size_t)b * T_ * C_ + h * S_);
    float4* xs4w = reinterpret_cast<float4*>(xs);
    #pragma unroll 5
    for (int idx = tid; idx < XROWS * 16; idx += NTHREADS) {
        int row  = idx >> 4;
        int col4 = idx & 15;
        int t    = t0 + row - PAD_;
        float4 v = make_float4(0.f, 0.f, 0.f, 0.f);
        if (t >= 0 && t < T_) v = xbase4[(size_t)t * (C_ / 4) + col4];
        xs4w[idx] = v;
    }

    // ---- softmax over K=31 taps: warp per t-row, lane = k; 2 rows/iter for ILP ----
    const float* fbase = filters + (size_t)b * T_ * HK_ + h * K_;
    for (int row = warp; row < TTILE; row += 16) {
        int rowB = row + 8;
        float fA = -1e30f, fB = -1e30f;
        if (lane < K_) {
            fA = fbase[(size_t)(t0 + row)  * HK_ + lane];
            fB = fbase[(size_t)(t0 + rowB) * HK_ + lane];
        }
        float mA = fA, mB = fB;
        #pragma unroll
        for (int o = 16; o > 0; o >>= 1) {
            mA = fmaxf(mA, __shfl_xor_sync(0xffffffffu, mA, o));
            mB = fmaxf(mB, __shfl_xor_sync(0xffffffffu, mB, o));
        }
        float eA = (lane < K_) ? __expf(fA - mA) : 0.0f;
        float eB = (lane < K_) ? __expf(fB - mB) : 0.0f;
        float sA = eA, sB = eB;
        #pragma unroll
        for (int o = 16; o > 0; o >>= 1) {
            sA += __shfl_xor_sync(0xffffffffu, sA, o);
            sB += __shfl_xor_sync(0xffffffffu, sB, o);
        }
        if (lane < K_) {
            ws[lane * WSTRIDE + row]  = eA * (1.0f / sA);   // bank=(lane+row)%32 conflict-free
            ws[lane * WSTRIDE + rowB] = eB * (1.0f / sB);
        }
    }
    __syncthreads();

    // ---- main product ----
    const int s4 = tid & 15;
    const int tg = tid >> 4;
    const int tl = tg * RT;

    const ulonglong2* xs2 = reinterpret_cast<const ulonglong2*>(xs) + s4;
    const float* wcol = ws + tl;   // w[t=tl+r][k=j-r] at wcol[(j-r)*WSTRIDE + r]

    // init accumulators with bias
    float4 bv = reinterpret_cast<const float4*>(bias + h * S_)[s4];
    u64 acc[RT][2];
    #pragma unroll
    for (int r = 0; r < RT; ++r) {
        acc[r][0] = pack2f(bv.x, bv.y);
        acc[r][1] = pack2f(bv.z, bv.w);
    }

    // Region 1: triangular prologue, compile-time guards
    #pragma unroll
    for (int j = 0; j < RT - 1; ++j) {
        ulonglong2 xv = xs2[(tl + j) * (S_ / 4)];
        float wf[RT];
        #pragma unroll
        for (int r = 0; r < RT; ++r)
            if (r <= j) wf[r] = wcol[(j - r) * WSTRIDE + r];
        #pragma unroll
        for (int r = 0; r < RT; ++r) {
            if (r <= j) {
                u64 w2 = pack2(wf[r]);
                fma2(acc[r][0], xv.x, w2);
                fma2(acc[r][1], xv.y, w2);
            }
        }
    }

    // Region 2: steady state. Two-phase body: 8 independent LDS hoisted into
    // f32 regs (8 regs), then pack+FMA. unroll 2 bounds live ranges -> <=64 regs.
    #pragma unroll 2
    for (int j = RT - 1; j < K_; ++j) {
        ulonglong2 xv = xs2[(tl + j) * (S_ / 4)];
        float wf[RT];
        #pragma unroll
        for (int r = 0; r < RT; ++r)
            wf[r] = wcol[(j - r) * WSTRIDE + r];
        #pragma unroll
        for (int r = 0; r < RT; ++r) {
            u64 w2 = pack2(wf[r]);
            fma2(acc[r][0], xv.x, w2);
            fma2(acc[r][1], xv.y, w2);
        }
    }

    // Region 3: triangular epilogue, compile-time guards
    #pragma unroll
    for (int j = K_; j < K_ + RT - 1; ++j) {
        ulonglong2 xv = xs2[(tl + j) * (S_ / 4)];
        float wf[RT];
        #pragma unroll
        for (int r = 0; r < RT; ++r)
            if (j - r < K_) wf[r] = wcol[(j - r) * WSTRIDE + r];
        #pragma unroll
        for (int r = 0; r < RT; ++r) {
            if (j - r < K_) {
                u64 w2 = pack2(wf[r]);
                fma2(acc[r][0], xv.x, w2);
                fma2(acc[r][1], xv.y, w2);
            }
        }
    }

    // ---- epilogue: vectorized store (bias already folded in) ----
    float4* outbase = reinterpret_cast<float4*>(
        out + ((size_t)b * T_ + t0 + tl) * C_ + h * S_) + s4;
    #pragma unroll
    for (int r = 0; r < RT; ++r) {
        float2 lo = unpack2(acc[r][0]);
        float2 hi = unpack2(acc[r][1]);
        float4 o;
        o.x = lo.x;
        o.y = lo.y;
        o.z = hi.x;
        o.w = hi.y;
        outbase[(size_t)r * (C_ / 4)] = o;
    }
}

extern "C" void kernel_launch(void* const* d_in, const int* in_sizes, int n_in,
                              void* d_out, int out_size)
{
    const float* x       = (const float*)d_in[0];
    const float* filters = (const float*)d_in[1];
    const float* bias    = (const float*)d_in[2];
    float* out           = (float*)d_out;

    cudaFuncSetAttribute(lightconv_kernel,
                         cudaFuncAttributeMaxDynamicSharedMemorySize, SMEM_BYTES);

    dim3 grid(T_ / TTILE, H_, B_);   // (8, 8, 8) = 512 CTAs, 4 CTAs/SM -> ~0.87 waves
    lightconv_kernel<<<grid, NTHREADS, SMEM_BYTES>>>(x, filters, bias, out);
}